// round 2
// baseline (speedup 1.0000x reference)
#include <cuda_runtime.h>
#include <cuda_bf16.h>

// Fused GNN, register-lean version.
// Key identities vs. round-1 kernel:
//   - encoder done j-outer (streams z one row at a time; za[80] never lives)
//   - predictor neighbor term: sum_g (z1[jm,g]+z1[jp,g])*wb[g] = v[jm]+v[jp],
//     v[j] = dot(z1[j], wb)  -> nn[80] never materialized
//   - __launch_bounds__(128,4): force 128 regs -> 16 warps/SM (was 246 -> 8)

__global__ void __launch_bounds__(128, 4) gnn_fused_kernel(
    const float* __restrict__ x,
    const float* __restrict__ z,
    const float* __restrict__ y,
    const float* __restrict__ enc_rel_w,
    const float* __restrict__ enc_rel_b,
    const float* __restrict__ enc_root_w,
    const float* __restrict__ pred_rel_w,
    const float* __restrict__ pred_rel_b,
    const float* __restrict__ pred_root_w,
    const float* __restrict__ dec_rel_w,
    const float* __restrict__ dec_rel_b,
    const float* __restrict__ dec_root_w,
    float* __restrict__ out,
    int B)
{
    __shared__ __align__(16) float sWRt[64];  // enc_root_w transposed: [g][f]
    __shared__ __align__(16) float sWA[64];   // pred_rel_w + pred_root_w  [f][g]
    __shared__ __align__(16) float sWB[64];   // w_edge * pred_rel_w       [f][g]
    __shared__ __align__(16) float sEW[8], sEB[8], sPB[8], sDW[8];
    __shared__ float sDB, sDR;

    const int tid = threadIdx.x;
    if (tid < 64) {
        const int f = tid >> 3, g = tid & 7;
        sWRt[g * 8 + f] = enc_root_w[tid];
        float pr = pred_rel_w[tid];
        sWA[tid] = pr + pred_root_w[tid];
        sWB[tid] = expf(-1.0f / 9.0f) * pr;   // np.float32(exp(-(1/3)^2))
    }
    if (tid < 8) {
        sEW[tid] = enc_rel_w[tid];
        sEB[tid] = enc_rel_b[tid];
        sPB[tid] = pred_rel_b[tid];
        sDW[tid] = dec_rel_w[tid];
    }
    if (tid == 0) { sDB = dec_rel_b[0]; sDR = dec_root_w[0]; }
    __syncthreads();

    const long long b = (long long)blockIdx.x * blockDim.x + tid;
    if (b >= B) return;

    // ---------- s[10] from x (xa is transient) ----------
    float s[10];
    {
        float xa[40];
        const float4* xp = reinterpret_cast<const float4*>(x + b * 40);
        #pragma unroll
        for (int i = 0; i < 10; i++) {
            float4 v = xp[i];
            xa[4*i+0] = v.x; xa[4*i+1] = v.y; xa[4*i+2] = v.z; xa[4*i+3] = v.w;
        }
        #pragma unroll
        for (int j = 0; j < 10; j++) {
            float a0 = xa[(4*j + 37) % 40] + xa[(4*j + 38) % 40];
            float a1 = xa[(4*j + 39) % 40] + xa[(4*j +  0) % 40];
            float a2 = xa[(4*j +  1) % 40] + xa[(4*j +  2) % 40];
            s[j] = (a0 + a1) + a2;
        }
    }

    // ---------- encoder, j-outer: stream z rows, accumulate over f ----------
    float z1[80];
    {
        const float4* zp = reinterpret_cast<const float4*>(z + b * 80);
        const float4* WRt4 = reinterpret_cast<const float4*>(sWRt);
        const float4* EW4  = reinterpret_cast<const float4*>(sEW);
        const float4* EB4  = reinterpret_cast<const float4*>(sEB);
        float4 ew0 = EW4[0], ew1 = EW4[1];
        float4 eb0 = EB4[0], eb1 = EB4[1];
        #pragma unroll
        for (int j = 0; j < 10; j++) {
            float4 za = zp[2*j];
            float4 zb = zp[2*j + 1];
            float acc[8];
            acc[0] = fmaf(s[j], ew0.x, eb0.x);
            acc[1] = fmaf(s[j], ew0.y, eb0.y);
            acc[2] = fmaf(s[j], ew0.z, eb0.z);
            acc[3] = fmaf(s[j], ew0.w, eb0.w);
            acc[4] = fmaf(s[j], ew1.x, eb1.x);
            acc[5] = fmaf(s[j], ew1.y, eb1.y);
            acc[6] = fmaf(s[j], ew1.z, eb1.z);
            acc[7] = fmaf(s[j], ew1.w, eb1.w);
            const float zv[8] = {za.x, za.y, za.z, za.w, zb.x, zb.y, zb.z, zb.w};
            #pragma unroll
            for (int g = 0; g < 8; g++) {
                float4 w0 = WRt4[2*g];
                float4 w1 = WRt4[2*g + 1];
                acc[0] = fmaf(zv[g], w0.x, acc[0]);
                acc[1] = fmaf(zv[g], w0.y, acc[1]);
                acc[2] = fmaf(zv[g], w0.z, acc[2]);
                acc[3] = fmaf(zv[g], w0.w, acc[3]);
                acc[4] = fmaf(zv[g], w1.x, acc[4]);
                acc[5] = fmaf(zv[g], w1.y, acc[5]);
                acc[6] = fmaf(zv[g], w1.z, acc[6]);
                acc[7] = fmaf(zv[g], w1.w, acc[7]);
            }
            #pragma unroll
            for (int f = 0; f < 8; f++) z1[j*8 + f] = fmaxf(acc[f], 0.0f);
        }
    }

    // ---------- predictor + decoder-rel fused, f-outer with v-trick ----------
    float t[10];
    #pragma unroll
    for (int j = 0; j < 10; j++) t[j] = 0.0f;

    {
        const float4* WA4 = reinterpret_cast<const float4*>(sWA);
        const float4* WB4 = reinterpret_cast<const float4*>(sWB);
        #pragma unroll
        for (int f = 0; f < 8; f++) {
            // v[j] = dot(z1[j], wb[f])
            float4 wb0 = WB4[2*f], wb1 = WB4[2*f + 1];
            float v[10];
            #pragma unroll
            for (int j = 0; j < 10; j++) {
                float p0 = z1[j*8+0] * wb0.x;
                float p1 = z1[j*8+1] * wb0.y;
                p0 = fmaf(z1[j*8+2], wb0.z, p0);
                p1 = fmaf(z1[j*8+3], wb0.w, p1);
                p0 = fmaf(z1[j*8+4], wb1.x, p0);
                p1 = fmaf(z1[j*8+5], wb1.y, p1);
                p0 = fmaf(z1[j*8+6], wb1.z, p0);
                p1 = fmaf(z1[j*8+7], wb1.w, p1);
                v[j] = p0 + p1;
            }
            float4 wa0 = WA4[2*f], wa1 = WA4[2*f + 1];
            const float pb = sPB[f], dw = sDW[f];
            #pragma unroll
            for (int j = 0; j < 10; j++) {
                const int jm = (j + 9) % 10, jp = (j + 1) % 10;
                float u0 = fmaf(z1[j*8+0], wa0.x, pb);
                float u1 = z1[j*8+1] * wa0.y;
                u0 = fmaf(z1[j*8+2], wa0.z, u0);
                u1 = fmaf(z1[j*8+3], wa0.w, u1);
                u0 = fmaf(z1[j*8+4], wa1.x, u0);
                u1 = fmaf(z1[j*8+5], wa1.y, u1);
                u0 = fmaf(z1[j*8+6], wa1.z, u0);
                u1 = fmaf(z1[j*8+7], wa1.w, u1);
                float pre = (u0 + u1) + (v[jm] + v[jp]);
                t[j] = fmaf(fmaxf(pre, 0.0f), dw, t[j]);
            }
        }
    }

    // ---------- decoder aggregation + root + output ----------
    const float dB = sDB, dR = sDR;
    const float4* yp = reinterpret_cast<const float4*>(y + b * 40);
    float4* op = reinterpret_cast<float4*>(out + b * 40);
    #pragma unroll
    for (int q = 0; q < 10; q++) {
        float4 yv = yp[q];
        float yc[4] = {yv.x, yv.y, yv.z, yv.w};
        float r[4];
        #pragma unroll
        for (int c = 0; c < 4; c++) {
            const int i = 4*q + c;
            const int jlo = ((i + 1) / 4) % 10;
            const int jhi = ((i + 3) / 4) % 10;
            float agg = t[jlo];
            if (jhi != jlo) agg += t[jhi];
            r[c] = fmaf(yc[c], dR, agg + dB);
        }
        op[q] = make_float4(r[0], r[1], r[2], r[3]);
    }
}

extern "C" void kernel_launch(void* const* d_in, const int* in_sizes, int n_in,
                              void* d_out, int out_size) {
    const float* x           = (const float*)d_in[0];
    const float* z           = (const float*)d_in[1];
    const float* y           = (const float*)d_in[2];
    const float* enc_rel_w   = (const float*)d_in[3];
    const float* enc_rel_b   = (const float*)d_in[4];
    const float* enc_root_w  = (const float*)d_in[5];
    const float* pred_rel_w  = (const float*)d_in[6];
    const float* pred_rel_b  = (const float*)d_in[7];
    const float* pred_root_w = (const float*)d_in[8];
    const float* dec_rel_w   = (const float*)d_in[9];
    const float* dec_rel_b   = (const float*)d_in[10];
    const float* dec_root_w  = (const float*)d_in[11];
    float* out = (float*)d_out;

    const int B = in_sizes[0] / 40;
    const int threads = 128;
    const int blocks = (B + threads - 1) / threads;
    gnn_fused_kernel<<<blocks, threads>>>(
        x, z, y, enc_rel_w, enc_rel_b, enc_root_w,
        pred_rel_w, pred_rel_b, pred_root_w,
        dec_rel_w, dec_rel_b, dec_root_w, out, B);
}

// round 3
// speedup vs baseline: 1.7623x; 1.7623x over previous
#include <cuda_runtime.h>
#include <cuda_bf16.h>

// Fused GNN, 2-threads-per-element version.
// Each element's 10-node ring is split across a lane pair (p = tid&1 handles
// nodes j in [5p, 5p+5)). Halves the per-thread live set (no z1[80]) so the
// kernel genuinely fits 128 regs without spills. Ring coupling crosses the
// pair at symmetric points -> shfl.bfly(1):
//   x:   partner's local x[17..19]            (3 shfls)
//   pred: partner's v[0], v[4] per feature f  (16 shfls)
//   dec: partner's t[0]                       (1 shfl)
// Math identities (validated in R1/R2):
//   s[j]    = sum_{d=-3..2} x[(4j+d) mod 40]
//   z1[j,f] = relu(s[j]*ew[f] + eb[f] + sum_g z[j,g]*WRt[g,f])
//   v[j]    = dot(z1[j], wb_f), wb = exp(-1/9)*pred_rel
//   pre2    = pb + dot(z1[j], wa_f) + v[j-1] + v[j+1], wa = pred_rel+pred_root
//   t[j]    = sum_f relu(pre2_f)*dw_f
//   out[i]  = t[(i+1)/4 %10] (+ t[(i+3)/4 %10]) + db + dr*y[i]

__global__ void __launch_bounds__(128, 4) gnn_fused_kernel(
    const float* __restrict__ x,
    const float* __restrict__ z,
    const float* __restrict__ y,
    const float* __restrict__ enc_rel_w,
    const float* __restrict__ enc_rel_b,
    const float* __restrict__ enc_root_w,
    const float* __restrict__ pred_rel_w,
    const float* __restrict__ pred_rel_b,
    const float* __restrict__ pred_root_w,
    const float* __restrict__ dec_rel_w,
    const float* __restrict__ dec_rel_b,
    const float* __restrict__ dec_root_w,
    float* __restrict__ out,
    long long NT)   // NT = 2*B threads total
{
    __shared__ __align__(16) float sWRt[64];  // enc_root_w transposed [g][f]
    __shared__ __align__(16) float sWA[64];   // pred_rel_w + pred_root_w [f][g]
    __shared__ __align__(16) float sWB[64];   // exp(-1/9) * pred_rel_w   [f][g]
    __shared__ __align__(16) float sEW[8], sEB[8], sPB[8], sDW[8];
    __shared__ float sDB, sDR;

    const int tid = threadIdx.x;
    if (tid < 64) {
        const int f = tid >> 3, g = tid & 7;
        sWRt[g * 8 + f] = enc_root_w[tid];
        float pr = pred_rel_w[tid];
        sWA[tid] = pr + pred_root_w[tid];
        sWB[tid] = expf(-1.0f / 9.0f) * pr;
    }
    if (tid < 8) {
        sEW[tid] = enc_rel_w[tid];
        sEB[tid] = enc_rel_b[tid];
        sPB[tid] = pred_rel_b[tid];
        sDW[tid] = dec_rel_w[tid];
    }
    if (tid == 0) { sDB = dec_rel_b[0]; sDR = dec_root_w[0]; }
    __syncthreads();

    const long long gt = (long long)blockIdx.x * blockDim.x + tid;
    if (gt >= NT) return;

    // ---------- loads: x (5 float4) and z (10 float4), fully coalesced ----------
    float xl[20];
    {
        const float4* xp = reinterpret_cast<const float4*>(x) + gt * 5;
        #pragma unroll
        for (int i = 0; i < 5; i++) {
            float4 v = xp[i];
            xl[4*i+0] = v.x; xl[4*i+1] = v.y; xl[4*i+2] = v.z; xl[4*i+3] = v.w;
        }
    }
    float4 zl[10];
    {
        const float4* zp = reinterpret_cast<const float4*>(z) + gt * 10;
        #pragma unroll
        for (int i = 0; i < 10; i++) zl[i] = zp[i];
    }

    // ---------- s[5]: boundary x from partner ----------
    float m0 = __shfl_xor_sync(0xFFFFFFFFu, xl[17], 1);
    float m1 = __shfl_xor_sync(0xFFFFFFFFu, xl[18], 1);
    float m2 = __shfl_xor_sync(0xFFFFFFFFu, xl[19], 1);

    float s[5];
    s[0] = ((m0 + m1) + (m2 + xl[0])) + (xl[1] + xl[2]);
    #pragma unroll
    for (int k = 1; k < 5; k++) {
        float a0 = xl[4*k - 3] + xl[4*k - 2];
        float a1 = xl[4*k - 1] + xl[4*k + 0];
        float a2 = xl[4*k + 1] + xl[4*k + 2];
        s[k] = (a0 + a1) + a2;
    }

    // ---------- encoder: z1[k][f] for this thread's 5 rows ----------
    float z1[40];
    {
        const float4* WRt4 = reinterpret_cast<const float4*>(sWRt);
        const float4* EW4  = reinterpret_cast<const float4*>(sEW);
        const float4* EB4  = reinterpret_cast<const float4*>(sEB);
        float4 ew0 = EW4[0], ew1 = EW4[1];
        float4 eb0 = EB4[0], eb1 = EB4[1];
        #pragma unroll
        for (int k = 0; k < 5; k++) {
            float4 za = zl[2*k], zb = zl[2*k + 1];
            const float zv[8] = {za.x, za.y, za.z, za.w, zb.x, zb.y, zb.z, zb.w};
            float acc[8];
            acc[0] = fmaf(s[k], ew0.x, eb0.x);
            acc[1] = fmaf(s[k], ew0.y, eb0.y);
            acc[2] = fmaf(s[k], ew0.z, eb0.z);
            acc[3] = fmaf(s[k], ew0.w, eb0.w);
            acc[4] = fmaf(s[k], ew1.x, eb1.x);
            acc[5] = fmaf(s[k], ew1.y, eb1.y);
            acc[6] = fmaf(s[k], ew1.z, eb1.z);
            acc[7] = fmaf(s[k], ew1.w, eb1.w);
            #pragma unroll
            for (int g = 0; g < 8; g++) {
                float4 w0 = WRt4[2*g];
                float4 w1 = WRt4[2*g + 1];
                acc[0] = fmaf(zv[g], w0.x, acc[0]);
                acc[1] = fmaf(zv[g], w0.y, acc[1]);
                acc[2] = fmaf(zv[g], w0.z, acc[2]);
                acc[3] = fmaf(zv[g], w0.w, acc[3]);
                acc[4] = fmaf(zv[g], w1.x, acc[4]);
                acc[5] = fmaf(zv[g], w1.y, acc[5]);
                acc[6] = fmaf(zv[g], w1.z, acc[6]);
                acc[7] = fmaf(zv[g], w1.w, acc[7]);
            }
            #pragma unroll
            for (int f = 0; f < 8; f++) z1[k*8 + f] = fmaxf(acc[f], 0.0f);
        }
    }

    // ---------- predictor + decoder-rel fused ----------
    float t[5] = {0.f, 0.f, 0.f, 0.f, 0.f};
    {
        const float4* WA4 = reinterpret_cast<const float4*>(sWA);
        const float4* WB4 = reinterpret_cast<const float4*>(sWB);
        #pragma unroll
        for (int f = 0; f < 8; f++) {
            float4 wb0 = WB4[2*f], wb1 = WB4[2*f + 1];
            float v[5];
            #pragma unroll
            for (int k = 0; k < 5; k++) {
                float p0 = z1[k*8+0] * wb0.x;
                float p1 = z1[k*8+1] * wb0.y;
                p0 = fmaf(z1[k*8+2], wb0.z, p0);
                p1 = fmaf(z1[k*8+3], wb0.w, p1);
                p0 = fmaf(z1[k*8+4], wb1.x, p0);
                p1 = fmaf(z1[k*8+5], wb1.y, p1);
                p0 = fmaf(z1[k*8+6], wb1.z, p0);
                p1 = fmaf(z1[k*8+7], wb1.w, p1);
                v[k] = p0 + p1;
            }
            // partner boundary v's: vm = partner v[4] (my jm at k=0),
            //                       vp = partner v[0] (my jp at k=4)
            float vm = __shfl_xor_sync(0xFFFFFFFFu, v[4], 1);
            float vp = __shfl_xor_sync(0xFFFFFFFFu, v[0], 1);

            float4 wa0 = WA4[2*f], wa1 = WA4[2*f + 1];
            const float pb = sPB[f], dw = sDW[f];
            #pragma unroll
            for (int k = 0; k < 5; k++) {
                float nb = (k == 0 ? vm : v[k-1]) + (k == 4 ? vp : v[k+1]);
                float u0 = fmaf(z1[k*8+0], wa0.x, pb);
                float u1 = z1[k*8+1] * wa0.y;
                u0 = fmaf(z1[k*8+2], wa0.z, u0);
                u1 = fmaf(z1[k*8+3], wa0.w, u1);
                u0 = fmaf(z1[k*8+4], wa1.x, u0);
                u1 = fmaf(z1[k*8+5], wa1.y, u1);
                u0 = fmaf(z1[k*8+6], wa1.z, u0);
                u1 = fmaf(z1[k*8+7], wa1.w, u1);
                float pre = (u0 + u1) + nb;
                t[k] = fmaf(fmaxf(pre, 0.0f), dw, t[k]);
            }
        }
    }

    // ---------- decoder aggregation + root + output ----------
    float T[6];
    #pragma unroll
    for (int k = 0; k < 5; k++) T[k] = t[k];
    T[5] = __shfl_xor_sync(0xFFFFFFFFu, t[0], 1);   // partner's first node

    const float dB = sDB, dR = sDR;
    const float4* yp = reinterpret_cast<const float4*>(y) + gt * 5;
    float4* op = reinterpret_cast<float4*>(out) + gt * 5;
    #pragma unroll
    for (int q = 0; q < 5; q++) {
        float4 yv = yp[q];
        float yc[4] = {yv.x, yv.y, yv.z, yv.w};
        float r[4];
        #pragma unroll
        for (int c = 0; c < 4; c++) {
            const int i = 4*q + c;          // local grid index 0..19
            const int lo = (i + 1) / 4;     // local t index, 5 -> partner
            const int hi = (i + 3) / 4;
            float agg = T[lo];
            if (hi != lo) agg += T[hi];
            r[c] = fmaf(yc[c], dR, agg + dB);
        }
        op[q] = make_float4(r[0], r[1], r[2], r[3]);
    }
}

extern "C" void kernel_launch(void* const* d_in, const int* in_sizes, int n_in,
                              void* d_out, int out_size) {
    const float* x           = (const float*)d_in[0];
    const float* z           = (const float*)d_in[1];
    const float* y           = (const float*)d_in[2];
    const float* enc_rel_w   = (const float*)d_in[3];
    const float* enc_rel_b   = (const float*)d_in[4];
    const float* enc_root_w  = (const float*)d_in[5];
    const float* pred_rel_w  = (const float*)d_in[6];
    const float* pred_rel_b  = (const float*)d_in[7];
    const float* pred_root_w = (const float*)d_in[8];
    const float* dec_rel_w   = (const float*)d_in[9];
    const float* dec_rel_b   = (const float*)d_in[10];
    const float* dec_root_w  = (const float*)d_in[11];
    float* out = (float*)d_out;

    const long long B  = in_sizes[0] / 40;
    const long long NT = 2 * B;                 // two threads per element
    const int threads = 128;
    const long long blocks = (NT + threads - 1) / threads;
    gnn_fused_kernel<<<(unsigned)blocks, threads>>>(
        x, z, y, enc_rel_w, enc_rel_b, enc_root_w,
        pred_rel_w, pred_rel_b, pred_root_w,
        dec_rel_w, dec_rel_b, dec_root_w, out, NT);
}

// round 4
// speedup vs baseline: 1.9102x; 1.0839x over previous
#include <cuda_runtime.h>
#include <cuda_bf16.h>

// Fused GNN, 2-threads-per-element + packed f32x2 math.
// Feature dimension (8) processed as 4 packed f32x2 lanes -> FFMA2 double-rate
// path on sm_103a. Scalar->pair broadcasts are MOVs on the (idle) alu pipe.

typedef unsigned long long u64;

static __device__ __forceinline__ u64 pk2(float a, float b) {
    u64 r; asm("mov.b64 %0, {%1, %2};" : "=l"(r) : "f"(a), "f"(b)); return r;
}
static __device__ __forceinline__ void upk2(u64 v, float& a, float& b) {
    asm("mov.b64 {%0, %1}, %2;" : "=f"(a), "=f"(b) : "l"(v));
}
static __device__ __forceinline__ u64 fma2(u64 a, u64 b, u64 c) {
    u64 d; asm("fma.rn.f32x2 %0, %1, %2, %3;" : "=l"(d) : "l"(a), "l"(b), "l"(c)); return d;
}
static __device__ __forceinline__ u64 add2(u64 a, u64 b) {
    u64 d; asm("add.rn.f32x2 %0, %1, %2;" : "=l"(d) : "l"(a), "l"(b)); return d;
}

__global__ void __launch_bounds__(128, 4) gnn_fused_kernel(
    const float* __restrict__ x,
    const float* __restrict__ z,
    const float* __restrict__ y,
    const float* __restrict__ enc_rel_w,
    const float* __restrict__ enc_rel_b,
    const float* __restrict__ enc_root_w,
    const float* __restrict__ pred_rel_w,
    const float* __restrict__ pred_rel_b,
    const float* __restrict__ pred_root_w,
    const float* __restrict__ dec_rel_w,
    const float* __restrict__ dec_rel_b,
    const float* __restrict__ dec_root_w,
    float* __restrict__ out,
    long long NT)   // NT = 2*B threads
{
    // Packed weights: pair = (f_even, f_odd) along the feature dim.
    __shared__ __align__(16) u64 sWRt2[32];  // [g][p]: (WRt[g][2p], WRt[g][2p+1]), WRt[g][f]=enc_root_w[f*8+g]
    __shared__ __align__(16) u64 sWA2[32];   // [fp][g]: wa = pred_rel + pred_root
    __shared__ __align__(16) u64 sWB2[32];   // [fp][g]: wb = exp(-1/9) * pred_rel
    __shared__ __align__(16) u64 sEW2[4], sEB2[4], sPB2[4];
    __shared__ float sDW[8];
    __shared__ float sDB, sDR;

    const int tid = threadIdx.x;
    if (tid < 32) {
        {
            const int g = tid >> 2, p = tid & 3;
            sWRt2[g * 4 + p] = pk2(enc_root_w[(2*p)*8 + g], enc_root_w[(2*p + 1)*8 + g]);
        }
        {
            const int fp = tid >> 3, g = tid & 7;
            const float w = expf(-1.0f / 9.0f);
            float pr0 = pred_rel_w[(2*fp)*8 + g],   pr1 = pred_rel_w[(2*fp + 1)*8 + g];
            float po0 = pred_root_w[(2*fp)*8 + g],  po1 = pred_root_w[(2*fp + 1)*8 + g];
            sWA2[fp * 8 + g] = pk2(pr0 + po0, pr1 + po1);
            sWB2[fp * 8 + g] = pk2(w * pr0, w * pr1);
        }
    }
    if (tid < 4) {
        sEW2[tid] = pk2(enc_rel_w[2*tid], enc_rel_w[2*tid + 1]);
        sEB2[tid] = pk2(enc_rel_b[2*tid], enc_rel_b[2*tid + 1]);
        sPB2[tid] = pk2(pred_rel_b[2*tid], pred_rel_b[2*tid + 1]);
    }
    if (tid < 8) sDW[tid] = dec_rel_w[tid];
    if (tid == 0) { sDB = dec_rel_b[0]; sDR = dec_root_w[0]; }
    __syncthreads();

    const long long gt = (long long)blockIdx.x * blockDim.x + tid;
    if (gt >= NT) return;

    // ---------- coalesced loads ----------
    float xl[20];
    {
        const float4* xp = reinterpret_cast<const float4*>(x) + gt * 5;
        #pragma unroll
        for (int i = 0; i < 5; i++) {
            float4 v = xp[i];
            xl[4*i+0] = v.x; xl[4*i+1] = v.y; xl[4*i+2] = v.z; xl[4*i+3] = v.w;
        }
    }
    float zz[40];
    {
        const float4* zp = reinterpret_cast<const float4*>(z) + gt * 10;
        #pragma unroll
        for (int i = 0; i < 10; i++) {
            float4 v = zp[i];
            zz[4*i+0] = v.x; zz[4*i+1] = v.y; zz[4*i+2] = v.z; zz[4*i+3] = v.w;
        }
    }

    // ---------- s[5] (partner boundary via shfl) ----------
    float m0 = __shfl_xor_sync(0xFFFFFFFFu, xl[17], 1);
    float m1 = __shfl_xor_sync(0xFFFFFFFFu, xl[18], 1);
    float m2 = __shfl_xor_sync(0xFFFFFFFFu, xl[19], 1);
    float s[5];
    s[0] = ((m0 + m1) + (m2 + xl[0])) + (xl[1] + xl[2]);
    #pragma unroll
    for (int k = 1; k < 5; k++) {
        float a0 = xl[4*k - 3] + xl[4*k - 2];
        float a1 = xl[4*k - 1] + xl[4*k + 0];
        float a2 = xl[4*k + 1] + xl[4*k + 2];
        s[k] = (a0 + a1) + a2;
    }

    // ---------- encoder (packed): A[k][p] = f32x2 acc over feature pair p ----------
    float z1[40];
    {
        u64 A[20];
        u64 sk[5];
        #pragma unroll
        for (int k = 0; k < 5; k++) sk[k] = pk2(s[k], s[k]);
        #pragma unroll
        for (int p = 0; p < 4; p++) {
            u64 ew = sEW2[p], eb = sEB2[p];
            #pragma unroll
            for (int k = 0; k < 5; k++) A[k*4 + p] = fma2(sk[k], ew, eb);
        }
        #pragma unroll
        for (int g = 0; g < 8; g++) {
            u64 w0 = sWRt2[g*4 + 0];
            u64 w1 = sWRt2[g*4 + 1];
            u64 w2 = sWRt2[g*4 + 2];
            u64 w3 = sWRt2[g*4 + 3];
            #pragma unroll
            for (int k = 0; k < 5; k++) {
                u64 zg = pk2(zz[k*8 + g], zz[k*8 + g]);
                A[k*4 + 0] = fma2(zg, w0, A[k*4 + 0]);
                A[k*4 + 1] = fma2(zg, w1, A[k*4 + 1]);
                A[k*4 + 2] = fma2(zg, w2, A[k*4 + 2]);
                A[k*4 + 3] = fma2(zg, w3, A[k*4 + 3]);
            }
        }
        #pragma unroll
        for (int k = 0; k < 5; k++) {
            #pragma unroll
            for (int p = 0; p < 4; p++) {
                float a, b; upk2(A[k*4 + p], a, b);
                z1[k*8 + 2*p]     = fmaxf(a, 0.0f);
                z1[k*8 + 2*p + 1] = fmaxf(b, 0.0f);
            }
        }
    }

    // ---------- predictor + decoder-rel fused (packed feature pairs) ----------
    float t[5] = {0.f, 0.f, 0.f, 0.f, 0.f};
    #pragma unroll
    for (int fp = 0; fp < 4; fp++) {
        u64 wa[8], wb[8];
        #pragma unroll
        for (int g = 0; g < 8; g++) { wa[g] = sWA2[fp*8 + g]; wb[g] = sWB2[fp*8 + g]; }
        u64 pb = sPB2[fp];

        u64 u2[5], v2[5];
        #pragma unroll
        for (int k = 0; k < 5; k++) {
            u64 uv = pb, vv = 0ULL;
            #pragma unroll
            for (int g = 0; g < 8; g++) {
                u64 zg = pk2(z1[k*8 + g], z1[k*8 + g]);
                uv = fma2(zg, wa[g], uv);
                vv = fma2(zg, wb[g], vv);
            }
            u2[k] = uv; v2[k] = vv;
        }

        // partner boundary v's (pairwise shfl of both packed halves)
        float va, vb;
        upk2(v2[4], va, vb);
        float vma = __shfl_xor_sync(0xFFFFFFFFu, va, 1);
        float vmb = __shfl_xor_sync(0xFFFFFFFFu, vb, 1);
        u64 vm2 = pk2(vma, vmb);
        upk2(v2[0], va, vb);
        float vpa = __shfl_xor_sync(0xFFFFFFFFu, va, 1);
        float vpb = __shfl_xor_sync(0xFFFFFFFFu, vb, 1);
        u64 vp2 = pk2(vpa, vpb);

        const float dw0 = sDW[2*fp], dw1 = sDW[2*fp + 1];
        #pragma unroll
        for (int k = 0; k < 5; k++) {
            u64 nb  = add2(k == 0 ? vm2 : v2[k-1], k == 4 ? vp2 : v2[k+1]);
            u64 pre = add2(u2[k], nb);
            float p0, p1; upk2(pre, p0, p1);
            t[k] = fmaf(fmaxf(p0, 0.0f), dw0, t[k]);
            t[k] = fmaf(fmaxf(p1, 0.0f), dw1, t[k]);
        }
    }

    // ---------- decoder aggregation + root + output ----------
    float T[6];
    #pragma unroll
    for (int k = 0; k < 5; k++) T[k] = t[k];
    T[5] = __shfl_xor_sync(0xFFFFFFFFu, t[0], 1);

    const float dB = sDB, dR = sDR;
    const float4* yp = reinterpret_cast<const float4*>(y) + gt * 5;
    float4* op = reinterpret_cast<float4*>(out) + gt * 5;
    #pragma unroll
    for (int q = 0; q < 5; q++) {
        float4 yv = yp[q];
        float yc[4] = {yv.x, yv.y, yv.z, yv.w};
        float r[4];
        #pragma unroll
        for (int c = 0; c < 4; c++) {
            const int i = 4*q + c;
            const int lo = (i + 1) / 4;
            const int hi = (i + 3) / 4;
            float agg = T[lo];
            if (hi != lo) agg += T[hi];
            r[c] = fmaf(yc[c], dR, agg + dB);
        }
        op[q] = make_float4(r[0], r[1], r[2], r[3]);
    }
}

extern "C" void kernel_launch(void* const* d_in, const int* in_sizes, int n_in,
                              void* d_out, int out_size) {
    const float* x           = (const float*)d_in[0];
    const float* z           = (const float*)d_in[1];
    const float* y           = (const float*)d_in[2];
    const float* enc_rel_w   = (const float*)d_in[3];
    const float* enc_rel_b   = (const float*)d_in[4];
    const float* enc_root_w  = (const float*)d_in[5];
    const float* pred_rel_w  = (const float*)d_in[6];
    const float* pred_rel_b  = (const float*)d_in[7];
    const float* pred_root_w = (const float*)d_in[8];
    const float* dec_rel_w   = (const float*)d_in[9];
    const float* dec_rel_b   = (const float*)d_in[10];
    const float* dec_root_w  = (const float*)d_in[11];
    float* out = (float*)d_out;

    const long long B  = in_sizes[0] / 40;
    const long long NT = 2 * B;
    const int threads = 128;
    const long long blocks = (NT + threads - 1) / threads;
    gnn_fused_kernel<<<(unsigned)blocks, threads>>>(
        x, z, y, enc_rel_w, enc_rel_b, enc_root_w,
        pred_rel_w, pred_rel_b, pred_root_w,
        dec_rel_w, dec_rel_b, dec_root_w, out, NT);
}

// round 5
// speedup vs baseline: 1.9264x; 1.0085x over previous
#include <cuda_runtime.h>
#include <cuda_bf16.h>

// Fused GNN: 2 threads/element, f32x2 packed math, register-lean (weights kept
// in shared and re-read via broadcast LDS.128 instead of hoisted into regs),
// launch_bounds(128,5) -> 20 warps/SM.

typedef unsigned long long u64;

static __device__ __forceinline__ u64 pk2(float a, float b) {
    u64 r; asm("mov.b64 %0, {%1, %2};" : "=l"(r) : "f"(a), "f"(b)); return r;
}
static __device__ __forceinline__ void upk2(u64 v, float& a, float& b) {
    asm("mov.b64 {%0, %1}, %2;" : "=f"(a), "=f"(b) : "l"(v));
}
static __device__ __forceinline__ u64 fma2(u64 a, u64 b, u64 c) {
    u64 d; asm("fma.rn.f32x2 %0, %1, %2, %3;" : "=l"(d) : "l"(a), "l"(b), "l"(c)); return d;
}
static __device__ __forceinline__ u64 add2(u64 a, u64 b) {
    u64 d; asm("add.rn.f32x2 %0, %1, %2;" : "=l"(d) : "l"(a), "l"(b)); return d;
}

__global__ void __launch_bounds__(128, 5) gnn_fused_kernel(
    const float* __restrict__ x,
    const float* __restrict__ z,
    const float* __restrict__ y,
    const float* __restrict__ enc_rel_w,
    const float* __restrict__ enc_rel_b,
    const float* __restrict__ enc_root_w,
    const float* __restrict__ pred_rel_w,
    const float* __restrict__ pred_rel_b,
    const float* __restrict__ pred_root_w,
    const float* __restrict__ dec_rel_w,
    const float* __restrict__ dec_rel_b,
    const float* __restrict__ dec_root_w,
    float* __restrict__ out,
    long long NT)   // NT = 2*B threads
{
    // Packed weights (pair = feature (2p, 2p+1)):
    __shared__ __align__(16) u64 sWRt2[32];  // [g*4+p]: enc_root_w^T packed over f
    __shared__ __align__(16) u64 sW2[64];    // [(fp*8+g)*2 + {0:wa,1:wb}]
    __shared__ __align__(16) u64 sEW2[4], sEB2[4], sPB2[4];
    __shared__ float sDW[8];
    __shared__ float sDB, sDR;

    const int tid = threadIdx.x;
    if (tid < 32) {
        {
            const int g = tid >> 2, p = tid & 3;
            sWRt2[g * 4 + p] = pk2(enc_root_w[(2*p)*8 + g], enc_root_w[(2*p + 1)*8 + g]);
        }
        {
            const int fp = tid >> 3, g = tid & 7;
            const float w = expf(-1.0f / 9.0f);
            float pr0 = pred_rel_w[(2*fp)*8 + g],   pr1 = pred_rel_w[(2*fp + 1)*8 + g];
            float po0 = pred_root_w[(2*fp)*8 + g],  po1 = pred_root_w[(2*fp + 1)*8 + g];
            sW2[(fp*8 + g)*2 + 0] = pk2(pr0 + po0, pr1 + po1);   // wa
            sW2[(fp*8 + g)*2 + 1] = pk2(w * pr0, w * pr1);       // wb
        }
    }
    if (tid < 4) {
        sEW2[tid] = pk2(enc_rel_w[2*tid], enc_rel_w[2*tid + 1]);
        sEB2[tid] = pk2(enc_rel_b[2*tid], enc_rel_b[2*tid + 1]);
        sPB2[tid] = pk2(pred_rel_b[2*tid], pred_rel_b[2*tid + 1]);
    }
    if (tid < 8) sDW[tid] = dec_rel_w[tid];
    if (tid == 0) { sDB = dec_rel_b[0]; sDR = dec_root_w[0]; }
    __syncthreads();

    const long long gt = (long long)blockIdx.x * blockDim.x + tid;
    if (gt >= NT) return;

    // ---------- coalesced front-batched loads ----------
    float xl[20];
    {
        const float4* xp = reinterpret_cast<const float4*>(x) + gt * 5;
        #pragma unroll
        for (int i = 0; i < 5; i++) {
            float4 v = xp[i];
            xl[4*i+0] = v.x; xl[4*i+1] = v.y; xl[4*i+2] = v.z; xl[4*i+3] = v.w;
        }
    }
    float4 zl[10];
    {
        const float4* zp = reinterpret_cast<const float4*>(z) + gt * 10;
        #pragma unroll
        for (int i = 0; i < 10; i++) zl[i] = zp[i];
    }

    // ---------- s[5] ----------
    float m0 = __shfl_xor_sync(0xFFFFFFFFu, xl[17], 1);
    float m1 = __shfl_xor_sync(0xFFFFFFFFu, xl[18], 1);
    float m2 = __shfl_xor_sync(0xFFFFFFFFu, xl[19], 1);
    float s[5];
    s[0] = ((m0 + m1) + (m2 + xl[0])) + (xl[1] + xl[2]);
    #pragma unroll
    for (int k = 1; k < 5; k++) {
        float a0 = xl[4*k - 3] + xl[4*k - 2];
        float a1 = xl[4*k - 1] + xl[4*k + 0];
        float a2 = xl[4*k + 1] + xl[4*k + 2];
        s[k] = (a0 + a1) + a2;
    }

    // ---------- encoder, k-outer: A[4] packed accumulators per node ----------
    float z1[40];
    {
        const ulonglong2* EW = reinterpret_cast<const ulonglong2*>(sEW2);
        const ulonglong2* EB = reinterpret_cast<const ulonglong2*>(sEB2);
        const ulonglong2* WR = reinterpret_cast<const ulonglong2*>(sWRt2);
        #pragma unroll
        for (int k = 0; k < 5; k++) {
            float4 za = zl[2*k], zb = zl[2*k + 1];
            const float zv[8] = {za.x, za.y, za.z, za.w, zb.x, zb.y, zb.z, zb.w};
            u64 sk = pk2(s[k], s[k]);
            ulonglong2 ew01 = EW[0], ew23 = EW[1];
            ulonglong2 eb01 = EB[0], eb23 = EB[1];
            u64 A0 = fma2(sk, ew01.x, eb01.x);
            u64 A1 = fma2(sk, ew01.y, eb01.y);
            u64 A2 = fma2(sk, ew23.x, eb23.x);
            u64 A3 = fma2(sk, ew23.y, eb23.y);
            #pragma unroll
            for (int g = 0; g < 8; g++) {
                ulonglong2 w01 = WR[g*2];
                ulonglong2 w23 = WR[g*2 + 1];
                u64 zg = pk2(zv[g], zv[g]);
                A0 = fma2(zg, w01.x, A0);
                A1 = fma2(zg, w01.y, A1);
                A2 = fma2(zg, w23.x, A2);
                A3 = fma2(zg, w23.y, A3);
            }
            float a, b;
            upk2(A0, a, b); z1[k*8+0] = fmaxf(a, 0.f); z1[k*8+1] = fmaxf(b, 0.f);
            upk2(A1, a, b); z1[k*8+2] = fmaxf(a, 0.f); z1[k*8+3] = fmaxf(b, 0.f);
            upk2(A2, a, b); z1[k*8+4] = fmaxf(a, 0.f); z1[k*8+5] = fmaxf(b, 0.f);
            upk2(A3, a, b); z1[k*8+6] = fmaxf(a, 0.f); z1[k*8+7] = fmaxf(b, 0.f);
        }
    }

    // ---------- predictor + decoder-rel fused, (fp,g)-outer k-inner ----------
    float t[5] = {0.f, 0.f, 0.f, 0.f, 0.f};
    {
        const ulonglong2* W = reinterpret_cast<const ulonglong2*>(sW2);
        #pragma unroll
        for (int fp = 0; fp < 4; fp++) {
            u64 pb = sPB2[fp];
            u64 u2[5], v2[5];
            #pragma unroll
            for (int k = 0; k < 5; k++) { u2[k] = pb; v2[k] = 0ULL; }
            #pragma unroll
            for (int g = 0; g < 8; g++) {
                ulonglong2 w = W[fp*8 + g];   // {wa, wb}
                #pragma unroll
                for (int k = 0; k < 5; k++) {
                    u64 zg = pk2(z1[k*8 + g], z1[k*8 + g]);
                    u2[k] = fma2(zg, w.x, u2[k]);
                    v2[k] = fma2(zg, w.y, v2[k]);
                }
            }
            // partner boundary v's
            float va, vb;
            upk2(v2[4], va, vb);
            float vma = __shfl_xor_sync(0xFFFFFFFFu, va, 1);
            float vmb = __shfl_xor_sync(0xFFFFFFFFu, vb, 1);
            u64 vm2 = pk2(vma, vmb);
            upk2(v2[0], va, vb);
            float vpa = __shfl_xor_sync(0xFFFFFFFFu, va, 1);
            float vpb = __shfl_xor_sync(0xFFFFFFFFu, vb, 1);
            u64 vp2 = pk2(vpa, vpb);

            const float dw0 = sDW[2*fp], dw1 = sDW[2*fp + 1];
            #pragma unroll
            for (int k = 0; k < 5; k++) {
                u64 nb  = add2(k == 0 ? vm2 : v2[k-1], k == 4 ? vp2 : v2[k+1]);
                u64 pre = add2(u2[k], nb);
                float p0, p1; upk2(pre, p0, p1);
                t[k] = fmaf(fmaxf(p0, 0.0f), dw0, t[k]);
                t[k] = fmaf(fmaxf(p1, 0.0f), dw1, t[k]);
            }
        }
    }

    // ---------- decoder aggregation + root + output ----------
    float T[6];
    #pragma unroll
    for (int k = 0; k < 5; k++) T[k] = t[k];
    T[5] = __shfl_xor_sync(0xFFFFFFFFu, t[0], 1);

    const float dB = sDB, dR = sDR;
    const float4* yp = reinterpret_cast<const float4*>(y) + gt * 5;
    float4* op = reinterpret_cast<float4*>(out) + gt * 5;
    #pragma unroll
    for (int q = 0; q < 5; q++) {
        float4 yv = yp[q];
        float yc[4] = {yv.x, yv.y, yv.z, yv.w};
        float r[4];
        #pragma unroll
        for (int c = 0; c < 4; c++) {
            const int i = 4*q + c;
            const int lo = (i + 1) / 4;
            const int hi = (i + 3) / 4;
            float agg = T[lo];
            if (hi != lo) agg += T[hi];
            r[c] = fmaf(yc[c], dR, agg + dB);
        }
        op[q] = make_float4(r[0], r[1], r[2], r[3]);
    }
}

extern "C" void kernel_launch(void* const* d_in, const int* in_sizes, int n_in,
                              void* d_out, int out_size) {
    const float* x           = (const float*)d_in[0];
    const float* z           = (const float*)d_in[1];
    const float* y           = (const float*)d_in[2];
    const float* enc_rel_w   = (const float*)d_in[3];
    const float* enc_rel_b   = (const float*)d_in[4];
    const float* enc_root_w  = (const float*)d_in[5];
    const float* pred_rel_w  = (const float*)d_in[6];
    const float* pred_rel_b  = (const float*)d_in[7];
    const float* pred_root_w = (const float*)d_in[8];
    const float* dec_rel_w   = (const float*)d_in[9];
    const float* dec_rel_b   = (const float*)d_in[10];
    const float* dec_root_w  = (const float*)d_in[11];
    float* out = (float*)d_out;

    const long long B  = in_sizes[0] / 40;
    const long long NT = 2 * B;
    const int threads = 128;
    const long long blocks = (NT + threads - 1) / threads;
    gnn_fused_kernel<<<(unsigned)blocks, threads>>>(
        x, z, y, enc_rel_w, enc_rel_b, enc_root_w,
        pred_rel_w, pred_rel_b, pred_root_w,
        dec_rel_w, dec_rel_b, dec_root_w, out, NT);
}